// round 2
// baseline (speedup 1.0000x reference)
#include <cuda_runtime.h>
#include <cuda_bf16.h>
#include <math.h>

// ---------------- Problem constants ----------------
#define T_SEQ   2048
#define HID     5120
#define NH      16
#define D_NOPE  128
#define D_ROPE  64
#define D_V     128
#define Q_LORA  1536
#define KV_LORA 512
#define QK_HD   (D_NOPE + D_ROPE)   // 192
#define KVA_N   (KV_LORA + D_ROPE)  // 576
#define QB_N    (NH * QK_HD)        // 3072
#define KVB_N   (NH * (D_NOPE + D_V)) // 4096
#define O_K     (NH * D_V)          // 2048

static const float SCALE = 0.07216878364870322f; // 192^-0.5
#define EPS_RMS 1e-6f

// ---------------- Scratch (static device globals; no allocation) ----------------
__device__ float g_qa   [T_SEQ * Q_LORA];          // hs @ w_qa
__device__ float g_qc   [T_SEQ * Q_LORA];          // rmsnorm(g_qa)
__device__ float g_q    [T_SEQ * QB_N];            // g_qc @ w_qb
__device__ float g_kv   [T_SEQ * KVA_N];           // hs @ w_kva
__device__ float g_kvc  [T_SEQ * KV_LORA];         // rmsnorm(g_kv[:, :512])
__device__ float g_kvup [T_SEQ * KVB_N];           // g_kvc @ w_kvb
__device__ float g_qfull[(long)NH * T_SEQ * QK_HD];// [h][t][192]
__device__ float g_kfull[(long)NH * T_SEQ * QK_HD];// [h][t][192]
__device__ float g_v    [(long)NH * T_SEQ * D_V];  // [h][t][128]
__device__ float g_scores[(long)NH * T_SEQ * T_SEQ]; // [h][t][s], 268MB
__device__ float g_attn [T_SEQ * O_K];             // [t][h*128+d]

// ---------------- Generic tiled SGEMM ----------------
// C[M,N] = alpha * A @ B    (TRANSB==0 : B is K x N row-major)
//          alpha * A @ B^T  (TRANSB==1 : B is N x K row-major)
// Batched over blockIdx.z via element strides. CAUSAL==1 skips block tiles
// strictly above the diagonal (their outputs are never read).
#define BM 128
#define BN 128
#define BK 8
#define TM 8
#define TN 8

template<int TRANSB, int CAUSAL>
__global__ __launch_bounds__(256)
void sgemm_kernel(const float* __restrict__ A, const float* __restrict__ B,
                  float* __restrict__ C,
                  int M, int N, int K, int lda, int ldb, int ldc,
                  long strideA, long strideB, long strideC, float alpha)
{
    int row0 = blockIdx.y * BM;
    int col0 = blockIdx.x * BN;
    if (CAUSAL && col0 > row0 + (BM - 1)) return; // fully masked tile

    A += (long)blockIdx.z * strideA;
    B += (long)blockIdx.z * strideB;
    C += (long)blockIdx.z * strideC;

    __shared__ float As[BK][BM];
    __shared__ float Bs[BK][BN];

    int tid = threadIdx.x;
    int tx  = tid % 16;   // 16 x 16 thread grid
    int ty  = tid / 16;

    float acc[TM][TN];
#pragma unroll
    for (int i = 0; i < TM; i++)
#pragma unroll
        for (int j = 0; j < TN; j++) acc[i][j] = 0.f;

    // A-tile load mapping: 128 rows x 8 k, 4 elems/thread
    int aRow = tid >> 1;          // 0..127
    int aK0  = (tid & 1) * 4;     // 0 or 4

    // B-tile load mapping
    int bIdxA = tid >> 1;         // NT: n index 0..127
    int bK0   = (tid & 1) * 4;    // NT: k offset
    int bRowN = tid >> 5;         // NN: k index 0..7
    int bColN = (tid & 31) * 4;   // NN: n offset

    for (int k0 = 0; k0 < K; k0 += BK) {
#pragma unroll
        for (int i = 0; i < 4; i++) {
            int r = row0 + aRow, c = k0 + aK0 + i;
            As[aK0 + i][aRow] = (r < M && c < K) ? A[(long)r * lda + c] : 0.f;
        }
        if (TRANSB) {
#pragma unroll
            for (int i = 0; i < 4; i++) {
                int n = col0 + bIdxA, c = k0 + bK0 + i;
                Bs[bK0 + i][bIdxA] = (n < N && c < K) ? B[(long)n * ldb + c] : 0.f;
            }
        } else {
#pragma unroll
            for (int i = 0; i < 4; i++) {
                int r = k0 + bRowN, n = col0 + bColN + i;
                Bs[bRowN][bColN + i] = (r < K && n < N) ? B[(long)r * ldb + n] : 0.f;
            }
        }
        __syncthreads();

#pragma unroll
        for (int kk = 0; kk < BK; kk++) {
            float a[TM], b[TN];
#pragma unroll
            for (int i = 0; i < TM; i++) a[i] = As[kk][ty * TM + i];
#pragma unroll
            for (int j = 0; j < TN; j++) b[j] = Bs[kk][tx * TN + j];
#pragma unroll
            for (int i = 0; i < TM; i++)
#pragma unroll
                for (int j = 0; j < TN; j++) acc[i][j] += a[i] * b[j];
        }
        __syncthreads();
    }

#pragma unroll
    for (int i = 0; i < TM; i++) {
        int r = row0 + ty * TM + i;
        if (r >= M) continue;
#pragma unroll
        for (int j = 0; j < TN; j++) {
            int c = col0 + tx * TN + j;
            if (c < N) C[(long)r * ldc + c] = alpha * acc[i][j];
        }
    }
}

// ---------------- RMSNorm ----------------
__global__ void rmsnorm_kernel(const float* __restrict__ in,
                               const float* __restrict__ w,
                               float* __restrict__ out,
                               int L, int inStride, int outStride)
{
    int t = blockIdx.x;
    const float* x = in + (long)t * inStride;
    float*       y = out + (long)t * outStride;

    float ss = 0.f;
    for (int i = threadIdx.x; i < L; i += blockDim.x) {
        float v = x[i]; ss += v * v;
    }
    __shared__ float sh[33];
#pragma unroll
    for (int o = 16; o; o >>= 1) ss += __shfl_xor_sync(~0u, ss, o);
    int lane = threadIdx.x & 31, wrp = threadIdx.x >> 5;
    if (lane == 0) sh[wrp] = ss;
    __syncthreads();
    if (wrp == 0) {
        float v = (lane < (blockDim.x >> 5)) ? sh[lane] : 0.f;
#pragma unroll
        for (int o = 16; o; o >>= 1) v += __shfl_xor_sync(~0u, v, o);
        if (lane == 0) sh[32] = v;
    }
    __syncthreads();
    float r = rsqrtf(sh[32] / (float)L + EPS_RMS);
    for (int i = threadIdx.x; i < L; i += blockDim.x)
        y[i] = x[i] * r * w[i];
}

// ---------------- RoPE + repack into [h][t][...] layouts ----------------
__global__ void pack_rope_kernel(const int* __restrict__ positions,
                                 const float* __restrict__ q,      // [t][h*192+d]
                                 const float* __restrict__ kvbuf,  // [t][576]
                                 const float* __restrict__ kvup,   // [t][h*256+d]
                                 float* __restrict__ qfull,        // [h][t][192]
                                 float* __restrict__ kfull,        // [h][t][192]
                                 float* __restrict__ vbuf)         // [h][t][128]
{
    int t   = blockIdx.x;
    int tid = threadIdx.x; // 256
    float pos = (float)positions[t];

    __shared__ float kp[D_ROPE];
    if (tid < 32) {
        int i = tid;
        float inv = expf(-logf(10000.0f) * (2.0f * i) / (float)D_ROPE);
        float ang = pos * inv;
        float c = cosf(ang), s = sinf(ang);
        float x1 = kvbuf[(long)t * KVA_N + KV_LORA + 2 * i];
        float x2 = kvbuf[(long)t * KVA_N + KV_LORA + 2 * i + 1];
        kp[2 * i]     = x1 * c - x2 * s;
        kp[2 * i + 1] = x2 * c + x1 * s;
    }
    __syncthreads();

    // nope copies + broadcast roped k_pe
    for (int idx = tid; idx < NH * QK_HD; idx += blockDim.x) {
        int h = idx / QK_HD, d = idx % QK_HD;
        long dst = ((long)h * T_SEQ + t) * QK_HD + d;
        if (d < D_NOPE) {
            qfull[dst] = q   [(long)t * QB_N  + h * QK_HD + d];
            kfull[dst] = kvup[(long)t * KVB_N + h * (D_NOPE + D_V) + d];
        } else {
            kfull[dst] = kp[d - D_NOPE];
        }
    }
    // q_pe rope
    for (int idx = tid; idx < NH * (D_ROPE / 2); idx += blockDim.x) {
        int h = idx / (D_ROPE / 2), i = idx % (D_ROPE / 2);
        float inv = expf(-logf(10000.0f) * (2.0f * i) / (float)D_ROPE);
        float ang = pos * inv;
        float c = cosf(ang), s = sinf(ang);
        long src = (long)t * QB_N + h * QK_HD + D_NOPE;
        float x1 = q[src + 2 * i];
        float x2 = q[src + 2 * i + 1];
        long dst = ((long)h * T_SEQ + t) * QK_HD + D_NOPE;
        qfull[dst + 2 * i]     = x1 * c - x2 * s;
        qfull[dst + 2 * i + 1] = x2 * c + x1 * s;
    }
    // v pack
    for (int idx = tid; idx < NH * D_V; idx += blockDim.x) {
        int h = idx / D_V, d = idx % D_V;
        vbuf[((long)h * T_SEQ + t) * D_V + d] =
            kvup[(long)t * KVB_N + h * (D_NOPE + D_V) + D_NOPE + d];
    }
}

// ---------------- Causal softmax over scores rows ----------------
__global__ void softmax_causal_kernel(float* __restrict__ scores)
{
    int t = blockIdx.x, h = blockIdx.y;
    float* row = scores + ((long)h * T_SEQ + t) * T_SEQ;
    int n = t + 1;

    __shared__ float sh[33];
    int lane = threadIdx.x & 31, wrp = threadIdx.x >> 5;

    // max
    float m = -INFINITY;
    for (int i = threadIdx.x; i < n; i += blockDim.x) m = fmaxf(m, row[i]);
#pragma unroll
    for (int o = 16; o; o >>= 1) m = fmaxf(m, __shfl_xor_sync(~0u, m, o));
    if (lane == 0) sh[wrp] = m;
    __syncthreads();
    if (wrp == 0) {
        float v = (lane < (blockDim.x >> 5)) ? sh[lane] : -INFINITY;
#pragma unroll
        for (int o = 16; o; o >>= 1) v = fmaxf(v, __shfl_xor_sync(~0u, v, o));
        if (lane == 0) sh[32] = v;
    }
    __syncthreads();
    m = sh[32];
    __syncthreads();

    // exp + sum
    float s = 0.f;
    for (int i = threadIdx.x; i < n; i += blockDim.x) {
        float e = expf(row[i] - m);
        row[i] = e;
        s += e;
    }
#pragma unroll
    for (int o = 16; o; o >>= 1) s += __shfl_xor_sync(~0u, s, o);
    if (lane == 0) sh[wrp] = s;
    __syncthreads();
    if (wrp == 0) {
        float v = (lane < (blockDim.x >> 5)) ? sh[lane] : 0.f;
#pragma unroll
        for (int o = 16; o; o >>= 1) v += __shfl_xor_sync(~0u, v, o);
        if (lane == 0) sh[32] = v;
    }
    __syncthreads();
    float inv = 1.0f / sh[32];

    for (int i = threadIdx.x; i < n; i += blockDim.x) row[i] *= inv;
    // zero the masked tail so P @ V is a plain GEMM
    for (int i = n + threadIdx.x; i < T_SEQ; i += blockDim.x) row[i] = 0.f;
}

// ---------------- Launch ----------------
extern "C" void kernel_launch(void* const* d_in, const int* in_sizes, int n_in,
                              void* d_out, int out_size)
{
    const int*   positions = (const int*)  d_in[0];
    const float* hs        = (const float*)d_in[1];
    const float* w_qa      = (const float*)d_in[2];
    const float* qa_ln_w   = (const float*)d_in[3];
    const float* w_qb      = (const float*)d_in[4];
    const float* w_kva     = (const float*)d_in[5];
    const float* kva_ln_w  = (const float*)d_in[6];
    const float* w_kvb     = (const float*)d_in[7];
    const float* w_o       = (const float*)d_in[8];
    float* out = (float*)d_out;

    float *p_qa, *p_qc, *p_q, *p_kv, *p_kvc, *p_kvup, *p_qf, *p_kf, *p_v, *p_sc, *p_at;
    cudaGetSymbolAddress((void**)&p_qa,   g_qa);
    cudaGetSymbolAddress((void**)&p_qc,   g_qc);
    cudaGetSymbolAddress((void**)&p_q,    g_q);
    cudaGetSymbolAddress((void**)&p_kv,   g_kv);
    cudaGetSymbolAddress((void**)&p_kvc,  g_kvc);
    cudaGetSymbolAddress((void**)&p_kvup, g_kvup);
    cudaGetSymbolAddress((void**)&p_qf,   g_qfull);
    cudaGetSymbolAddress((void**)&p_kf,   g_kfull);
    cudaGetSymbolAddress((void**)&p_v,    g_v);
    cudaGetSymbolAddress((void**)&p_sc,   g_scores);
    cudaGetSymbolAddress((void**)&p_at,   g_attn);

    dim3 blk(256);
    auto cdiv = [](int a, int b) { return (a + b - 1) / b; };

    // G1: qa = hs @ w_qa  (2048 x 1536, K=5120)
    sgemm_kernel<0,0><<<dim3(cdiv(Q_LORA,BN), cdiv(T_SEQ,BM), 1), blk>>>(
        hs, w_qa, p_qa, T_SEQ, Q_LORA, HID, HID, Q_LORA, Q_LORA, 0, 0, 0, 1.f);

    // G2: kv = hs @ w_kva (2048 x 576, K=5120)
    sgemm_kernel<0,0><<<dim3(cdiv(KVA_N,BN), cdiv(T_SEQ,BM), 1), blk>>>(
        hs, w_kva, p_kv, T_SEQ, KVA_N, HID, HID, KVA_N, KVA_N, 0, 0, 0, 1.f);

    // RMSNorms
    rmsnorm_kernel<<<T_SEQ, 256>>>(p_qa, qa_ln_w, p_qc, Q_LORA, Q_LORA, Q_LORA);
    rmsnorm_kernel<<<T_SEQ, 256>>>(p_kv, kva_ln_w, p_kvc, KV_LORA, KVA_N, KV_LORA);

    // G3: q = qc @ w_qb (2048 x 3072, K=1536)
    sgemm_kernel<0,0><<<dim3(cdiv(QB_N,BN), cdiv(T_SEQ,BM), 1), blk>>>(
        p_qc, w_qb, p_q, T_SEQ, QB_N, Q_LORA, Q_LORA, QB_N, QB_N, 0, 0, 0, 1.f);

    // G4: kvup = kvc @ w_kvb (2048 x 4096, K=512)
    sgemm_kernel<0,0><<<dim3(cdiv(KVB_N,BN), cdiv(T_SEQ,BM), 1), blk>>>(
        p_kvc, w_kvb, p_kvup, T_SEQ, KVB_N, KV_LORA, KV_LORA, KVB_N, KVB_N, 0, 0, 0, 1.f);

    // RoPE + repack
    pack_rope_kernel<<<T_SEQ, 256>>>(positions, p_q, p_kv, p_kvup, p_qf, p_kf, p_v);

    // G5: scores[h] = SCALE * qfull[h] @ kfull[h]^T  (causal tile skip)
    sgemm_kernel<1,1><<<dim3(cdiv(T_SEQ,BN), cdiv(T_SEQ,BM), NH), blk>>>(
        p_qf, p_kf, p_sc, T_SEQ, T_SEQ, QK_HD, QK_HD, QK_HD, T_SEQ,
        (long)T_SEQ * QK_HD, (long)T_SEQ * QK_HD, (long)T_SEQ * T_SEQ, SCALE);

    // softmax rows (zero masked tail)
    softmax_causal_kernel<<<dim3(T_SEQ, NH), 256>>>(p_sc);

    // G6: attn[t][h*128+d] = P[h] @ V[h]
    sgemm_kernel<0,0><<<dim3(cdiv(D_V,BN), cdiv(T_SEQ,BM), NH), blk>>>(
        p_sc, p_v, p_at, T_SEQ, D_V, T_SEQ, T_SEQ, D_V, O_K,
        (long)T_SEQ * T_SEQ, (long)T_SEQ * D_V, (long)D_V, 1.f);

    // G7: out = attn @ w_o (2048 x 5120, K=2048)
    sgemm_kernel<0,0><<<dim3(cdiv(HID,BN), cdiv(T_SEQ,BM), 1), blk>>>(
        p_at, w_o, out, T_SEQ, HID, O_K, O_K, HID, HID, 0, 0, 0, 1.f);
}

// round 3
// speedup vs baseline: 1.6000x; 1.6000x over previous
#include <cuda_runtime.h>
#include <cuda_bf16.h>
#include <math.h>

// ---------------- Problem constants ----------------
#define T_SEQ   2048
#define HID     5120
#define NH      16
#define D_NOPE  128
#define D_ROPE  64
#define D_V     128
#define Q_LORA  1536
#define KV_LORA 512
#define QK_HD   (D_NOPE + D_ROPE)   // 192
#define KVA_N   (KV_LORA + D_ROPE)  // 576
#define QB_N    (NH * QK_HD)        // 3072
#define KVB_N   (NH * (D_NOPE + D_V)) // 4096
#define O_K     (NH * D_V)          // 2048

static const float SCALE = 0.07216878364870322f; // 192^-0.5
#define EPS_RMS 1e-6f

// ---------------- Scratch (static device globals; no allocation) ----------------
__device__ float g_qa   [T_SEQ * Q_LORA];
__device__ float g_qc   [T_SEQ * Q_LORA];
__device__ float g_q    [T_SEQ * QB_N];
__device__ float g_kv   [T_SEQ * KVA_N];
__device__ float g_kvc  [T_SEQ * KV_LORA];
__device__ float g_kvup [T_SEQ * KVB_N];
__device__ float g_qfull[(long)NH * T_SEQ * QK_HD];
__device__ float g_kfull[(long)NH * T_SEQ * QK_HD];
__device__ float g_v    [(long)NH * T_SEQ * D_V];
__device__ float g_scores[(long)NH * T_SEQ * T_SEQ];
__device__ float g_attn [T_SEQ * O_K];

// ---------------- Optimized tiled SGEMM ----------------
// C[M,N] = alpha * A @ B    (TRANSB==0 : B is K x N row-major)
//          alpha * A @ B^T  (TRANSB==1 : B is N x K row-major)
// Requirements exploited (all call sites satisfy them):
//   M % 128 == 0, K % 16 == 0, lda/ldb/ldc % 4 == 0, N % 4 == 0.
//   TRANSB path additionally assumes N % 128 == 0 (G5 only, N=2048).
// CAUSAL  : skip output tiles strictly above the diagonal.
// CAUSAL_K: truncate the K loop at row0+BM (P rows are zero beyond t).
#define BM 128
#define BN 128
#define BK 16
#define SPAD 4

template<int TRANSB, int CAUSAL, int CAUSAL_K>
__global__ __launch_bounds__(256, 2)
void sgemm_kernel(const float* __restrict__ A, const float* __restrict__ B,
                  float* __restrict__ C,
                  int M, int N, int K, int lda, int ldb, int ldc,
                  long strideA, long strideB, long strideC, float alpha)
{
    __shared__ float As[2][BK][BM + SPAD];
    __shared__ float Bs[2][BK][BN + SPAD];

    int row0 = blockIdx.y * BM;
    int col0 = blockIdx.x * BN;
    if (CAUSAL && col0 > row0 + (BM - 1)) return;

    A += (long)blockIdx.z * strideA;
    B += (long)blockIdx.z * strideB;
    C += (long)blockIdx.z * strideC;

    int tid = threadIdx.x;
    int tx  = tid & 15;
    int ty  = tid >> 4;

    // A (and NT-B) load mapping: float4 along K. f = tid, tid+256.
    int aRow = tid >> 2;          // 0..63 (+64 for second half)
    int aKc  = (tid & 3) * 4;     // k offset within BK

    // NN-B load mapping: float4 along N. f = tid, tid+256.
    int bKr  = tid >> 5;          // 0..7 (+8 for second half)
    int bNc  = (tid & 31) * 4;    // n offset within BN

    float acc[8][8];
#pragma unroll
    for (int i = 0; i < 8; i++)
#pragma unroll
        for (int j = 0; j < 8; j++) acc[i][j] = 0.f;

    float4 ra[2], rb[2];

    auto loadA = [&](int k0) {
#pragma unroll
        for (int u = 0; u < 2; u++) {
            int r = row0 + aRow + u * 64;
            ra[u] = *reinterpret_cast<const float4*>(&A[(long)r * lda + k0 + aKc]);
        }
    };
    auto storeA = [&](int b) {
#pragma unroll
        for (int u = 0; u < 2; u++) {
            int r = aRow + u * 64;
            As[b][aKc + 0][r] = ra[u].x;
            As[b][aKc + 1][r] = ra[u].y;
            As[b][aKc + 2][r] = ra[u].z;
            As[b][aKc + 3][r] = ra[u].w;
        }
    };
    auto loadB = [&](int k0) {
        if (TRANSB) {
#pragma unroll
            for (int u = 0; u < 2; u++) {
                int n = col0 + aRow + u * 64;
                rb[u] = *reinterpret_cast<const float4*>(&B[(long)n * ldb + k0 + aKc]);
            }
        } else {
#pragma unroll
            for (int u = 0; u < 2; u++) {
                int k = k0 + bKr + u * 8;
                int n = col0 + bNc;
                rb[u] = (n < N) ? *reinterpret_cast<const float4*>(&B[(long)k * ldb + n])
                                : make_float4(0.f, 0.f, 0.f, 0.f);
            }
        }
    };
    auto storeB = [&](int b) {
        if (TRANSB) {
#pragma unroll
            for (int u = 0; u < 2; u++) {
                int n = aRow + u * 64;
                Bs[b][aKc + 0][n] = rb[u].x;
                Bs[b][aKc + 1][n] = rb[u].y;
                Bs[b][aKc + 2][n] = rb[u].z;
                Bs[b][aKc + 3][n] = rb[u].w;
            }
        } else {
#pragma unroll
            for (int u = 0; u < 2; u++) {
                int k = bKr + u * 8;
                *reinterpret_cast<float4*>(&Bs[b][k][bNc]) = rb[u];
            }
        }
    };
    auto compute = [&](int b) {
#pragma unroll
        for (int kk = 0; kk < BK; kk++) {
            float af[8], bf[8];
            *reinterpret_cast<float4*>(af)     = *reinterpret_cast<const float4*>(&As[b][kk][ty * 8]);
            *reinterpret_cast<float4*>(af + 4) = *reinterpret_cast<const float4*>(&As[b][kk][ty * 8 + 4]);
            *reinterpret_cast<float4*>(bf)     = *reinterpret_cast<const float4*>(&Bs[b][kk][tx * 8]);
            *reinterpret_cast<float4*>(bf + 4) = *reinterpret_cast<const float4*>(&Bs[b][kk][tx * 8 + 4]);
#pragma unroll
            for (int i = 0; i < 8; i++)
#pragma unroll
                for (int j = 0; j < 8; j++)
                    acc[i][j] += af[i] * bf[j];
        }
    };

    int kEnd = K;
    if (CAUSAL_K) { int lim = row0 + BM; kEnd = lim < K ? lim : K; }

    // Prologue
    loadA(0); loadB(0);
    storeA(0); storeB(0);
    __syncthreads();

    int buf = 0;
    for (int k0 = BK; k0 < kEnd; k0 += BK) {
        loadA(k0); loadB(k0);          // global loads for next tile (latency hidden)
        compute(buf);                  // compute on current tile
        storeA(buf ^ 1); storeB(buf ^ 1);
        __syncthreads();
        buf ^= 1;
    }
    compute(buf);

    // Epilogue (vectorized; N % 4 == 0 at all call sites)
#pragma unroll
    for (int i = 0; i < 8; i++) {
        int r = row0 + ty * 8 + i;
#pragma unroll
        for (int jv = 0; jv < 2; jv++) {
            int c = col0 + tx * 8 + jv * 4;
            if (c < N) {
                float4 v = make_float4(alpha * acc[i][jv * 4 + 0],
                                       alpha * acc[i][jv * 4 + 1],
                                       alpha * acc[i][jv * 4 + 2],
                                       alpha * acc[i][jv * 4 + 3]);
                *reinterpret_cast<float4*>(&C[(long)r * ldc + c]) = v;
            }
        }
    }
}

// ---------------- RMSNorm ----------------
__global__ void rmsnorm_kernel(const float* __restrict__ in,
                               const float* __restrict__ w,
                               float* __restrict__ out,
                               int L, int inStride, int outStride)
{
    int t = blockIdx.x;
    const float* x = in + (long)t * inStride;
    float*       y = out + (long)t * outStride;

    float ss = 0.f;
    for (int i = threadIdx.x; i < L; i += blockDim.x) {
        float v = x[i]; ss += v * v;
    }
    __shared__ float sh[33];
#pragma unroll
    for (int o = 16; o; o >>= 1) ss += __shfl_xor_sync(~0u, ss, o);
    int lane = threadIdx.x & 31, wrp = threadIdx.x >> 5;
    if (lane == 0) sh[wrp] = ss;
    __syncthreads();
    if (wrp == 0) {
        float v = (lane < (blockDim.x >> 5)) ? sh[lane] : 0.f;
#pragma unroll
        for (int o = 16; o; o >>= 1) v += __shfl_xor_sync(~0u, v, o);
        if (lane == 0) sh[32] = v;
    }
    __syncthreads();
    float r = rsqrtf(sh[32] / (float)L + EPS_RMS);
    for (int i = threadIdx.x; i < L; i += blockDim.x)
        y[i] = x[i] * r * w[i];
}

// ---------------- RoPE + repack into [h][t][...] layouts ----------------
__global__ void pack_rope_kernel(const int* __restrict__ positions,
                                 const float* __restrict__ q,      // [t][h*192+d]
                                 const float* __restrict__ kvbuf,  // [t][576]
                                 const float* __restrict__ kvup,   // [t][h*256+d]
                                 float* __restrict__ qfull,        // [h][t][192]
                                 float* __restrict__ kfull,        // [h][t][192]
                                 float* __restrict__ vbuf)         // [h][t][128]
{
    int t   = blockIdx.x;
    int tid = threadIdx.x; // 256
    float pos = (float)positions[t];

    __shared__ float kp[D_ROPE];
    if (tid < 32) {
        int i = tid;
        float inv = expf(-logf(10000.0f) * (2.0f * i) / (float)D_ROPE);
        float ang = pos * inv;
        float c = cosf(ang), s = sinf(ang);
        float x1 = kvbuf[(long)t * KVA_N + KV_LORA + 2 * i];
        float x2 = kvbuf[(long)t * KVA_N + KV_LORA + 2 * i + 1];
        kp[2 * i]     = x1 * c - x2 * s;
        kp[2 * i + 1] = x2 * c + x1 * s;
    }
    __syncthreads();

    for (int idx = tid; idx < NH * QK_HD; idx += blockDim.x) {
        int h = idx / QK_HD, d = idx % QK_HD;
        long dst = ((long)h * T_SEQ + t) * QK_HD + d;
        if (d < D_NOPE) {
            qfull[dst] = q   [(long)t * QB_N  + h * QK_HD + d];
            kfull[dst] = kvup[(long)t * KVB_N + h * (D_NOPE + D_V) + d];
        } else {
            kfull[dst] = kp[d - D_NOPE];
        }
    }
    for (int idx = tid; idx < NH * (D_ROPE / 2); idx += blockDim.x) {
        int h = idx / (D_ROPE / 2), i = idx % (D_ROPE / 2);
        float inv = expf(-logf(10000.0f) * (2.0f * i) / (float)D_ROPE);
        float ang = pos * inv;
        float c = cosf(ang), s = sinf(ang);
        long src = (long)t * QB_N + h * QK_HD + D_NOPE;
        float x1 = q[src + 2 * i];
        float x2 = q[src + 2 * i + 1];
        long dst = ((long)h * T_SEQ + t) * QK_HD + D_NOPE;
        qfull[dst + 2 * i]     = x1 * c - x2 * s;
        qfull[dst + 2 * i + 1] = x2 * c + x1 * s;
    }
    for (int idx = tid; idx < NH * D_V; idx += blockDim.x) {
        int h = idx / D_V, d = idx % D_V;
        vbuf[((long)h * T_SEQ + t) * D_V + d] =
            kvup[(long)t * KVB_N + h * (D_NOPE + D_V) + D_NOPE + d];
    }
}

// ---------------- Causal softmax over scores rows ----------------
__global__ void softmax_causal_kernel(float* __restrict__ scores)
{
    int t = blockIdx.x, h = blockIdx.y;
    float* row = scores + ((long)h * T_SEQ + t) * T_SEQ;
    int n = t + 1;

    __shared__ float sh[33];
    int lane = threadIdx.x & 31, wrp = threadIdx.x >> 5;

    float m = -INFINITY;
    for (int i = threadIdx.x; i < n; i += blockDim.x) m = fmaxf(m, row[i]);
#pragma unroll
    for (int o = 16; o; o >>= 1) m = fmaxf(m, __shfl_xor_sync(~0u, m, o));
    if (lane == 0) sh[wrp] = m;
    __syncthreads();
    if (wrp == 0) {
        float v = (lane < (blockDim.x >> 5)) ? sh[lane] : -INFINITY;
#pragma unroll
        for (int o = 16; o; o >>= 1) v = fmaxf(v, __shfl_xor_sync(~0u, v, o));
        if (lane == 0) sh[32] = v;
    }
    __syncthreads();
    m = sh[32];
    __syncthreads();

    float s = 0.f;
    for (int i = threadIdx.x; i < n; i += blockDim.x) {
        float e = expf(row[i] - m);
        row[i] = e;
        s += e;
    }
#pragma unroll
    for (int o = 16; o; o >>= 1) s += __shfl_xor_sync(~0u, s, o);
    if (lane == 0) sh[wrp] = s;
    __syncthreads();
    if (wrp == 0) {
        float v = (lane < (blockDim.x >> 5)) ? sh[lane] : 0.f;
#pragma unroll
        for (int o = 16; o; o >>= 1) v += __shfl_xor_sync(~0u, v, o);
        if (lane == 0) sh[32] = v;
    }
    __syncthreads();
    float inv = 1.0f / sh[32];

    for (int i = threadIdx.x; i < n; i += blockDim.x) row[i] *= inv;
    for (int i = n + threadIdx.x; i < T_SEQ; i += blockDim.x) row[i] = 0.f;
}

// ---------------- Launch ----------------
extern "C" void kernel_launch(void* const* d_in, const int* in_sizes, int n_in,
                              void* d_out, int out_size)
{
    const int*   positions = (const int*)  d_in[0];
    const float* hs        = (const float*)d_in[1];
    const float* w_qa      = (const float*)d_in[2];
    const float* qa_ln_w   = (const float*)d_in[3];
    const float* w_qb      = (const float*)d_in[4];
    const float* w_kva     = (const float*)d_in[5];
    const float* kva_ln_w  = (const float*)d_in[6];
    const float* w_kvb     = (const float*)d_in[7];
    const float* w_o       = (const float*)d_in[8];
    float* out = (float*)d_out;

    float *p_qa, *p_qc, *p_q, *p_kv, *p_kvc, *p_kvup, *p_qf, *p_kf, *p_v, *p_sc, *p_at;
    cudaGetSymbolAddress((void**)&p_qa,   g_qa);
    cudaGetSymbolAddress((void**)&p_qc,   g_qc);
    cudaGetSymbolAddress((void**)&p_q,    g_q);
    cudaGetSymbolAddress((void**)&p_kv,   g_kv);
    cudaGetSymbolAddress((void**)&p_kvc,  g_kvc);
    cudaGetSymbolAddress((void**)&p_kvup, g_kvup);
    cudaGetSymbolAddress((void**)&p_qf,   g_qfull);
    cudaGetSymbolAddress((void**)&p_kf,   g_kfull);
    cudaGetSymbolAddress((void**)&p_v,    g_v);
    cudaGetSymbolAddress((void**)&p_sc,   g_scores);
    cudaGetSymbolAddress((void**)&p_at,   g_attn);

    dim3 blk(256);
    auto cdiv = [](int a, int b) { return (a + b - 1) / b; };

    // G1: qa = hs @ w_qa  (2048 x 1536, K=5120)
    sgemm_kernel<0,0,0><<<dim3(cdiv(Q_LORA,BN), cdiv(T_SEQ,BM), 1), blk>>>(
        hs, w_qa, p_qa, T_SEQ, Q_LORA, HID, HID, Q_LORA, Q_LORA, 0, 0, 0, 1.f);

    // G2: kv = hs @ w_kva (2048 x 576, K=5120)
    sgemm_kernel<0,0,0><<<dim3(cdiv(KVA_N,BN), cdiv(T_SEQ,BM), 1), blk>>>(
        hs, w_kva, p_kv, T_SEQ, KVA_N, HID, HID, KVA_N, KVA_N, 0, 0, 0, 1.f);

    rmsnorm_kernel<<<T_SEQ, 256>>>(p_qa, qa_ln_w, p_qc, Q_LORA, Q_LORA, Q_LORA);
    rmsnorm_kernel<<<T_SEQ, 256>>>(p_kv, kva_ln_w, p_kvc, KV_LORA, KVA_N, KV_LORA);

    // G3: q = qc @ w_qb (2048 x 3072, K=1536)
    sgemm_kernel<0,0,0><<<dim3(cdiv(QB_N,BN), cdiv(T_SEQ,BM), 1), blk>>>(
        p_qc, w_qb, p_q, T_SEQ, QB_N, Q_LORA, Q_LORA, QB_N, QB_N, 0, 0, 0, 1.f);

    // G4: kvup = kvc @ w_kvb (2048 x 4096, K=512)
    sgemm_kernel<0,0,0><<<dim3(cdiv(KVB_N,BN), cdiv(T_SEQ,BM), 1), blk>>>(
        p_kvc, w_kvb, p_kvup, T_SEQ, KVB_N, KV_LORA, KV_LORA, KVB_N, KVB_N, 0, 0, 0, 1.f);

    pack_rope_kernel<<<T_SEQ, 256>>>(positions, p_q, p_kv, p_kvup, p_qf, p_kf, p_v);

    // G5: scores[h] = SCALE * qfull[h] @ kfull[h]^T  (causal tile skip)
    sgemm_kernel<1,1,0><<<dim3(cdiv(T_SEQ,BN), cdiv(T_SEQ,BM), NH), blk>>>(
        p_qf, p_kf, p_sc, T_SEQ, T_SEQ, QK_HD, QK_HD, QK_HD, T_SEQ,
        (long)T_SEQ * QK_HD, (long)T_SEQ * QK_HD, (long)T_SEQ * T_SEQ, SCALE);

    softmax_causal_kernel<<<dim3(T_SEQ, NH), 256>>>(p_sc);

    // G6: attn[t][h*128+d] = P[h] @ V[h]  (K truncated at row0+BM — P tail is zero)
    sgemm_kernel<0,0,1><<<dim3(cdiv(D_V,BN), cdiv(T_SEQ,BM), NH), blk>>>(
        p_sc, p_v, p_at, T_SEQ, D_V, T_SEQ, T_SEQ, D_V, O_K,
        (long)T_SEQ * T_SEQ, (long)T_SEQ * D_V, (long)D_V, 1.f);

    // G7: out = attn @ w_o (2048 x 5120, K=2048)
    sgemm_kernel<0,0,0><<<dim3(cdiv(HID,BN), cdiv(T_SEQ,BM), 1), blk>>>(
        p_at, w_o, out, T_SEQ, HID, O_K, O_K, HID, HID, 0, 0, 0, 1.f);
}

// round 4
// speedup vs baseline: 3.4506x; 2.1566x over previous
#include <cuda_runtime.h>
#include <cuda_bf16.h>
#include <math.h>
#include <stdint.h>

// ---------------- Problem constants ----------------
#define T_SEQ   2048
#define HID     5120
#define NH      16
#define D_NOPE  128
#define D_ROPE  64
#define D_V     128
#define Q_LORA  1536
#define KV_LORA 512
#define QK_HD   (D_NOPE + D_ROPE)   // 192
#define KVA_N   (KV_LORA + D_ROPE)  // 576
#define QB_N    (NH * QK_HD)        // 3072
#define KVB_N   (NH * (D_NOPE + D_V)) // 4096
#define O_K     (NH * D_V)          // 2048

static const float SCALE = 0.07216878364870322f; // 192^-0.5
#define EPS_RMS 1e-6f

// ---------------- Scratch ----------------
__device__ float g_qa   [T_SEQ * Q_LORA];
__device__ float g_qc   [T_SEQ * Q_LORA];
__device__ float g_q    [T_SEQ * QB_N];
__device__ float g_kv   [T_SEQ * KVA_N];
__device__ float g_kvc  [T_SEQ * KV_LORA];
__device__ float g_kvup [T_SEQ * KVB_N];
__device__ float g_qfull[(long)NH * T_SEQ * QK_HD];
__device__ float g_kfull[(long)NH * T_SEQ * QK_HD];
__device__ float g_v    [(long)NH * T_SEQ * D_V];
__device__ float g_scores[(long)NH * T_SEQ * T_SEQ];
__device__ float g_attn [T_SEQ * O_K];

// ---------------- Tensor-core GEMM (bf16 3-term split, fp32 accuracy) ----------------
// C[M,N] = alpha * A @ B    (TRANSB==0 : B is K x N row-major)
//          alpha * A @ B^T  (TRANSB==1 : B is N x K row-major)
// Assumes: M % 128 == 0, K % 16 == 0, N % 8 == 0, pointers 16B-aligned rows.
// CAUSAL:  skip output tiles strictly above the diagonal (batched z = head).
// CAUSAL_K: truncate K loop at row0+BM (P rows are zero beyond t).
#define BM 128
#define BN 128
#define BK 16

__device__ __forceinline__ uint32_t smem_u32(const void* p) {
    return (uint32_t)__cvta_generic_to_shared(p);
}
__device__ __forceinline__ void ldsm_x4(uint32_t addr, uint32_t r[4]) {
    asm volatile("ldmatrix.sync.aligned.m8n8.x4.shared.b16 {%0,%1,%2,%3}, [%4];"
                 : "=r"(r[0]), "=r"(r[1]), "=r"(r[2]), "=r"(r[3]) : "r"(addr));
}
__device__ __forceinline__ void ldsm_x4_t(uint32_t addr, uint32_t r[4]) {
    asm volatile("ldmatrix.sync.aligned.m8n8.x4.trans.shared.b16 {%0,%1,%2,%3}, [%4];"
                 : "=r"(r[0]), "=r"(r[1]), "=r"(r[2]), "=r"(r[3]) : "r"(addr));
}
__device__ __forceinline__ void mma_bf16(float c[4], const uint32_t a[4],
                                         uint32_t b0, uint32_t b1) {
    asm volatile(
        "mma.sync.aligned.m16n8k16.row.col.f32.bf16.bf16.f32 "
        "{%0,%1,%2,%3}, {%4,%5,%6,%7}, {%8,%9}, {%0,%1,%2,%3};"
        : "+f"(c[0]), "+f"(c[1]), "+f"(c[2]), "+f"(c[3])
        : "r"(a[0]), "r"(a[1]), "r"(a[2]), "r"(a[3]), "r"(b0), "r"(b1));
}
__device__ __forceinline__ uint32_t pack2(__nv_bfloat16 a, __nv_bfloat16 b) {
    __nv_bfloat162 t = __halves2bfloat162(a, b);
    return *reinterpret_cast<uint32_t*>(&t);
}
// Convert 8 floats (two float4) into hi/lo uint4 (8 bf16 each).
__device__ __forceinline__ void cvt8(const float4 v0, const float4 v1,
                                     uint4& hq, uint4& lq) {
    float f[8] = {v0.x, v0.y, v0.z, v0.w, v1.x, v1.y, v1.z, v1.w};
    __nv_bfloat16 h[8], l[8];
#pragma unroll
    for (int i = 0; i < 8; i++) {
        h[i] = __float2bfloat16(f[i]);
        l[i] = __float2bfloat16(f[i] - __bfloat162float(h[i]));
    }
    hq = make_uint4(pack2(h[0], h[1]), pack2(h[2], h[3]), pack2(h[4], h[5]), pack2(h[6], h[7]));
    lq = make_uint4(pack2(l[0], l[1]), pack2(l[2], l[3]), pack2(l[4], l[5]), pack2(l[6], l[7]));
}

template<int TRANSB, int CAUSAL, int CAUSAL_K>
__global__ __launch_bounds__(256)
void tgemm_kernel(const float* __restrict__ A, const float* __restrict__ B,
                  float* __restrict__ C,
                  int M, int N, int K, int lda, int ldb, int ldc,
                  long strideA, long strideB, long strideC, float alpha)
{
    constexpr int AST   = BK + 8;                 // 24 (padded k-stride)
    constexpr int BROWS = TRANSB ? BN : BK;
    constexpr int BST   = TRANSB ? (BK + 8) : (BN + 8);

    __shared__ __nv_bfloat16 Ah[2][BM][AST];
    __shared__ __nv_bfloat16 Al[2][BM][AST];
    __shared__ __nv_bfloat16 Bh[2][BROWS][BST];
    __shared__ __nv_bfloat16 Bl[2][BROWS][BST];

    int row0 = blockIdx.y * BM;
    int col0 = blockIdx.x * BN;
    if (CAUSAL && col0 > row0 + (BM - 1)) return;

    A += (long)blockIdx.z * strideA;
    B += (long)blockIdx.z * strideB;
    C += (long)blockIdx.z * strideC;

    int tid  = threadIdx.x;
    int lane = tid & 31;
    int warp = tid >> 5;
    int wm   = warp >> 1;   // 0..3
    int wn   = warp & 1;    // 0..1

    // A-tile (and TR B-tile) loader mapping: float4 pairs along K
    int aRow = tid >> 1;          // 0..127
    int aKc  = (tid & 1) * 8;     // 0 or 8
    // NN B-tile loader mapping
    int bKr  = tid >> 4;          // 0..15
    int bNc  = (tid & 15) * 8;    // 0..120

    float4 ra0, ra1, rb0, rb1;

    auto loadA = [&](int k0) {
        const float* p = &A[(long)(row0 + aRow) * lda + k0 + aKc];
        ra0 = *reinterpret_cast<const float4*>(p);
        ra1 = *reinterpret_cast<const float4*>(p + 4);
    };
    auto loadB = [&](int k0) {
        if (TRANSB) {
            int n = col0 + aRow;
            if (n < N) {
                const float* p = &B[(long)n * ldb + k0 + aKc];
                rb0 = *reinterpret_cast<const float4*>(p);
                rb1 = *reinterpret_cast<const float4*>(p + 4);
            } else {
                rb0 = rb1 = make_float4(0.f, 0.f, 0.f, 0.f);
            }
        } else {
            int n = col0 + bNc;
            const float* p = &B[(long)(k0 + bKr) * ldb + n];
            rb0 = (n     < N) ? *reinterpret_cast<const float4*>(p)     : make_float4(0.f,0.f,0.f,0.f);
            rb1 = (n + 4 < N) ? *reinterpret_cast<const float4*>(p + 4) : make_float4(0.f,0.f,0.f,0.f);
        }
    };
    auto storeA = [&](int b) {
        uint4 hq, lq; cvt8(ra0, ra1, hq, lq);
        *reinterpret_cast<uint4*>(&Ah[b][aRow][aKc]) = hq;
        *reinterpret_cast<uint4*>(&Al[b][aRow][aKc]) = lq;
    };
    auto storeB = [&](int b) {
        uint4 hq, lq; cvt8(rb0, rb1, hq, lq);
        if (TRANSB) {
            *reinterpret_cast<uint4*>(&Bh[b][aRow][aKc]) = hq;
            *reinterpret_cast<uint4*>(&Bl[b][aRow][aKc]) = lq;
        } else {
            *reinterpret_cast<uint4*>(&Bh[b][bKr][bNc]) = hq;
            *reinterpret_cast<uint4*>(&Bl[b][bKr][bNc]) = lq;
        }
    };

    float acc[2][8][4];
#pragma unroll
    for (int i = 0; i < 2; i++)
#pragma unroll
        for (int j = 0; j < 8; j++)
#pragma unroll
            for (int q = 0; q < 4; q++) acc[i][j][q] = 0.f;

    auto compute = [&](int b) {
        uint32_t a_h[2][4], a_l[2][4];
#pragma unroll
        for (int mt = 0; mt < 2; mt++) {
            int r = wm * 32 + mt * 16 + (lane & 15);
            int c = (lane >> 4) * 8;
            ldsm_x4(smem_u32(&Ah[b][r][c]), a_h[mt]);
            ldsm_x4(smem_u32(&Al[b][r][c]), a_l[mt]);
        }
#pragma unroll
        for (int p = 0; p < 4; p++) {   // pairs of n-tiles
            uint32_t bh[4], bl[4];
            if (TRANSB) {
                int g  = lane >> 3;
                int rr = lane & 7;
                int n  = wn * 64 + p * 16 + ((g >> 1) << 3) + rr;
                int c  = (g & 1) * 8;
                ldsm_x4(smem_u32(&Bh[b][n][c]), bh);
                ldsm_x4(smem_u32(&Bl[b][n][c]), bl);
            } else {
                int r    = lane & 15;
                int half = lane >> 4;
                int c    = wn * 64 + p * 16 + half * 8;
                ldsm_x4_t(smem_u32(&Bh[b][r][c]), bh);
                ldsm_x4_t(smem_u32(&Bl[b][r][c]), bl);
            }
#pragma unroll
            for (int mt = 0; mt < 2; mt++)
#pragma unroll
                for (int j = 0; j < 2; j++) {
                    float* c4 = acc[mt][2 * p + j];
                    mma_bf16(c4, a_h[mt], bh[2 * j], bh[2 * j + 1]);
                    mma_bf16(c4, a_h[mt], bl[2 * j], bl[2 * j + 1]);
                    mma_bf16(c4, a_l[mt], bh[2 * j], bh[2 * j + 1]);
                }
        }
    };

    int kEnd = K;
    if (CAUSAL_K) { int lim = row0 + BM; kEnd = lim < K ? lim : K; }

    loadA(0); loadB(0);
    storeA(0); storeB(0);
    __syncthreads();

    int buf = 0;
    for (int k0 = BK; k0 < kEnd; k0 += BK) {
        loadA(k0); loadB(k0);
        compute(buf);
        storeA(buf ^ 1); storeB(buf ^ 1);
        __syncthreads();
        buf ^= 1;
    }
    compute(buf);

    // Epilogue
    int gid = lane >> 2, tig = lane & 3;
#pragma unroll
    for (int mt = 0; mt < 2; mt++) {
        int r = row0 + wm * 32 + mt * 16 + gid;
#pragma unroll
        for (int nt = 0; nt < 8; nt++) {
            int c = col0 + wn * 64 + nt * 8 + tig * 2;
            if (c < N) {
                float2 v0 = make_float2(alpha * acc[mt][nt][0], alpha * acc[mt][nt][1]);
                float2 v1 = make_float2(alpha * acc[mt][nt][2], alpha * acc[mt][nt][3]);
                *reinterpret_cast<float2*>(&C[(long)r * ldc + c])       = v0;
                *reinterpret_cast<float2*>(&C[(long)(r + 8) * ldc + c]) = v1;
            }
        }
    }
}

// ---------------- RMSNorm ----------------
__global__ void rmsnorm_kernel(const float* __restrict__ in,
                               const float* __restrict__ w,
                               float* __restrict__ out,
                               int L, int inStride, int outStride)
{
    int t = blockIdx.x;
    const float* x = in + (long)t * inStride;
    float*       y = out + (long)t * outStride;

    float ss = 0.f;
    for (int i = threadIdx.x; i < L; i += blockDim.x) {
        float v = x[i]; ss += v * v;
    }
    __shared__ float sh[33];
#pragma unroll
    for (int o = 16; o; o >>= 1) ss += __shfl_xor_sync(~0u, ss, o);
    int lane = threadIdx.x & 31, wrp = threadIdx.x >> 5;
    if (lane == 0) sh[wrp] = ss;
    __syncthreads();
    if (wrp == 0) {
        float v = (lane < (blockDim.x >> 5)) ? sh[lane] : 0.f;
#pragma unroll
        for (int o = 16; o; o >>= 1) v += __shfl_xor_sync(~0u, v, o);
        if (lane == 0) sh[32] = v;
    }
    __syncthreads();
    float r = rsqrtf(sh[32] / (float)L + EPS_RMS);
    for (int i = threadIdx.x; i < L; i += blockDim.x)
        y[i] = x[i] * r * w[i];
}

// ---------------- RoPE + repack ----------------
__global__ void pack_rope_kernel(const int* __restrict__ positions,
                                 const float* __restrict__ q,
                                 const float* __restrict__ kvbuf,
                                 const float* __restrict__ kvup,
                                 float* __restrict__ qfull,
                                 float* __restrict__ kfull,
                                 float* __restrict__ vbuf)
{
    int t   = blockIdx.x;
    int tid = threadIdx.x;
    float pos = (float)positions[t];

    __shared__ float kp[D_ROPE];
    if (tid < 32) {
        int i = tid;
        float inv = expf(-logf(10000.0f) * (2.0f * i) / (float)D_ROPE);
        float ang = pos * inv;
        float c = cosf(ang), s = sinf(ang);
        float x1 = kvbuf[(long)t * KVA_N + KV_LORA + 2 * i];
        float x2 = kvbuf[(long)t * KVA_N + KV_LORA + 2 * i + 1];
        kp[2 * i]     = x1 * c - x2 * s;
        kp[2 * i + 1] = x2 * c + x1 * s;
    }
    __syncthreads();

    for (int idx = tid; idx < NH * QK_HD; idx += blockDim.x) {
        int h = idx / QK_HD, d = idx % QK_HD;
        long dst = ((long)h * T_SEQ + t) * QK_HD + d;
        if (d < D_NOPE) {
            qfull[dst] = q   [(long)t * QB_N  + h * QK_HD + d];
            kfull[dst] = kvup[(long)t * KVB_N + h * (D_NOPE + D_V) + d];
        } else {
            kfull[dst] = kp[d - D_NOPE];
        }
    }
    for (int idx = tid; idx < NH * (D_ROPE / 2); idx += blockDim.x) {
        int h = idx / (D_ROPE / 2), i = idx % (D_ROPE / 2);
        float inv = expf(-logf(10000.0f) * (2.0f * i) / (float)D_ROPE);
        float ang = pos * inv;
        float c = cosf(ang), s = sinf(ang);
        long src = (long)t * QB_N + h * QK_HD + D_NOPE;
        float x1 = q[src + 2 * i];
        float x2 = q[src + 2 * i + 1];
        long dst = ((long)h * T_SEQ + t) * QK_HD + D_NOPE;
        qfull[dst + 2 * i]     = x1 * c - x2 * s;
        qfull[dst + 2 * i + 1] = x2 * c + x1 * s;
    }
    for (int idx = tid; idx < NH * D_V; idx += blockDim.x) {
        int h = idx / D_V, d = idx % D_V;
        vbuf[((long)h * T_SEQ + t) * D_V + d] =
            kvup[(long)t * KVB_N + h * (D_NOPE + D_V) + D_NOPE + d];
    }
}

// ---------------- Causal softmax ----------------
__global__ void softmax_causal_kernel(float* __restrict__ scores)
{
    int t = blockIdx.x, h = blockIdx.y;
    float* row = scores + ((long)h * T_SEQ + t) * T_SEQ;
    int n = t + 1;

    __shared__ float sh[33];
    int lane = threadIdx.x & 31, wrp = threadIdx.x >> 5;

    float m = -INFINITY;
    for (int i = threadIdx.x; i < n; i += blockDim.x) m = fmaxf(m, row[i]);
#pragma unroll
    for (int o = 16; o; o >>= 1) m = fmaxf(m, __shfl_xor_sync(~0u, m, o));
    if (lane == 0) sh[wrp] = m;
    __syncthreads();
    if (wrp == 0) {
        float v = (lane < (blockDim.x >> 5)) ? sh[lane] : -INFINITY;
#pragma unroll
        for (int o = 16; o; o >>= 1) v = fmaxf(v, __shfl_xor_sync(~0u, v, o));
        if (lane == 0) sh[32] = v;
    }
    __syncthreads();
    m = sh[32];
    __syncthreads();

    float s = 0.f;
    for (int i = threadIdx.x; i < n; i += blockDim.x) {
        float e = expf(row[i] - m);
        row[i] = e;
        s += e;
    }
#pragma unroll
    for (int o = 16; o; o >>= 1) s += __shfl_xor_sync(~0u, s, o);
    if (lane == 0) sh[wrp] = s;
    __syncthreads();
    if (wrp == 0) {
        float v = (lane < (blockDim.x >> 5)) ? sh[lane] : 0.f;
#pragma unroll
        for (int o = 16; o; o >>= 1) v += __shfl_xor_sync(~0u, v, o);
        if (lane == 0) sh[32] = v;
    }
    __syncthreads();
    float inv = 1.0f / sh[32];

    for (int i = threadIdx.x; i < n; i += blockDim.x) row[i] *= inv;
    for (int i = n + threadIdx.x; i < T_SEQ; i += blockDim.x) row[i] = 0.f;
}

// ---------------- Launch ----------------
extern "C" void kernel_launch(void* const* d_in, const int* in_sizes, int n_in,
                              void* d_out, int out_size)
{
    const int*   positions = (const int*)  d_in[0];
    const float* hs        = (const float*)d_in[1];
    const float* w_qa      = (const float*)d_in[2];
    const float* qa_ln_w   = (const float*)d_in[3];
    const float* w_qb      = (const float*)d_in[4];
    const float* w_kva     = (const float*)d_in[5];
    const float* kva_ln_w  = (const float*)d_in[6];
    const float* w_kvb     = (const float*)d_in[7];
    const float* w_o       = (const float*)d_in[8];
    float* out = (float*)d_out;

    float *p_qa, *p_qc, *p_q, *p_kv, *p_kvc, *p_kvup, *p_qf, *p_kf, *p_v, *p_sc, *p_at;
    cudaGetSymbolAddress((void**)&p_qa,   g_qa);
    cudaGetSymbolAddress((void**)&p_qc,   g_qc);
    cudaGetSymbolAddress((void**)&p_q,    g_q);
    cudaGetSymbolAddress((void**)&p_kv,   g_kv);
    cudaGetSymbolAddress((void**)&p_kvc,  g_kvc);
    cudaGetSymbolAddress((void**)&p_kvup, g_kvup);
    cudaGetSymbolAddress((void**)&p_qf,   g_qfull);
    cudaGetSymbolAddress((void**)&p_kf,   g_kfull);
    cudaGetSymbolAddress((void**)&p_v,    g_v);
    cudaGetSymbolAddress((void**)&p_sc,   g_scores);
    cudaGetSymbolAddress((void**)&p_at,   g_attn);

    dim3 blk(256);
    auto cdiv = [](int a, int b) { return (a + b - 1) / b; };

    // G1: qa = hs @ w_qa  (2048 x 1536, K=5120)
    tgemm_kernel<0,0,0><<<dim3(cdiv(Q_LORA,BN), cdiv(T_SEQ,BM), 1), blk>>>(
        hs, w_qa, p_qa, T_SEQ, Q_LORA, HID, HID, Q_LORA, Q_LORA, 0, 0, 0, 1.f);

    // G2: kv = hs @ w_kva (2048 x 576, K=5120)
    tgemm_kernel<0,0,0><<<dim3(cdiv(KVA_N,BN), cdiv(T_SEQ,BM), 1), blk>>>(
        hs, w_kva, p_kv, T_SEQ, KVA_N, HID, HID, KVA_N, KVA_N, 0, 0, 0, 1.f);

    rmsnorm_kernel<<<T_SEQ, 256>>>(p_qa, qa_ln_w, p_qc, Q_LORA, Q_LORA, Q_LORA);
    rmsnorm_kernel<<<T_SEQ, 256>>>(p_kv, kva_ln_w, p_kvc, KV_LORA, KVA_N, KV_LORA);

    // G3: q = qc @ w_qb (2048 x 3072, K=1536)
    tgemm_kernel<0,0,0><<<dim3(cdiv(QB_N,BN), cdiv(T_SEQ,BM), 1), blk>>>(
        p_qc, w_qb, p_q, T_SEQ, QB_N, Q_LORA, Q_LORA, QB_N, QB_N, 0, 0, 0, 1.f);

    // G4: kvup = kvc @ w_kvb (2048 x 4096, K=512)
    tgemm_kernel<0,0,0><<<dim3(cdiv(KVB_N,BN), cdiv(T_SEQ,BM), 1), blk>>>(
        p_kvc, w_kvb, p_kvup, T_SEQ, KVB_N, KV_LORA, KV_LORA, KVB_N, KVB_N, 0, 0, 0, 1.f);

    pack_rope_kernel<<<T_SEQ, 256>>>(positions, p_q, p_kv, p_kvup, p_qf, p_kf, p_v);

    // G5: scores[h] = SCALE * qfull[h] @ kfull[h]^T  (causal tile skip)
    tgemm_kernel<1,1,0><<<dim3(cdiv(T_SEQ,BN), cdiv(T_SEQ,BM), NH), blk>>>(
        p_qf, p_kf, p_sc, T_SEQ, T_SEQ, QK_HD, QK_HD, QK_HD, T_SEQ,
        (long)T_SEQ * QK_HD, (long)T_SEQ * QK_HD, (long)T_SEQ * T_SEQ, SCALE);

    softmax_causal_kernel<<<dim3(T_SEQ, NH), 256>>>(p_sc);

    // G6: attn = P[h] @ V[h]  (K truncated at row0+BM)
    tgemm_kernel<0,0,1><<<dim3(cdiv(D_V,BN), cdiv(T_SEQ,BM), NH), blk>>>(
        p_sc, p_v, p_at, T_SEQ, D_V, T_SEQ, T_SEQ, D_V, O_K,
        (long)T_SEQ * T_SEQ, (long)T_SEQ * D_V, (long)D_V, 1.f);

    // G7: out = attn @ w_o (2048 x 5120, K=2048)
    tgemm_kernel<0,0,0><<<dim3(cdiv(HID,BN), cdiv(T_SEQ,BM), 1), blk>>>(
        p_at, w_o, out, T_SEQ, HID, O_K, O_K, HID, HID, 0, 0, 0, 1.f);
}